// round 4
// baseline (speedup 1.0000x reference)
#include <cuda_runtime.h>
#include <cstdint>

// out[b,n,m] = sum_d x1[b,n,d]*x2[b,m,d] + const   (B=4, N=M=4096, D=32, fp32)
//
// Round 4: mma.sync tf32 + smem-bounce coalesced epilogue.
// R3 analysis: epilogue STG.64s hit 16 lines/instr -> 4096 L1 wavefronts/CTA
// (the 79% L1 ceiling). Now: acc -> smem -> full-line STG.128 (4 wf/instr),
// reusing the A/B smem in 2 chunks of 64 rows.

#define TILE 128
#define DDIM 32
#define ROW_WORDS 34                 // staging: 32 data + 2 pad words
#define TILE_WORDS (128 * ROW_WORDS) // 4352
#define C_STRIDE 132                 // epilogue: 128 data + 4 pad words

__device__ __forceinline__ uint32_t f32_to_tf32(float f) {
    uint32_t r;
    asm("cvt.rna.tf32.f32 %0, %1;" : "=r"(r) : "f"(f));
    return r;
}

__device__ __forceinline__ void mma_tf32_16x8x8(
    float& d0, float& d1, float& d2, float& d3,
    uint32_t a0, uint32_t a1, uint32_t a2, uint32_t a3,
    uint32_t b0, uint32_t b1) {
    asm volatile(
        "mma.sync.aligned.m16n8k8.row.col.f32.tf32.tf32.f32 "
        "{%0,%1,%2,%3}, {%4,%5,%6,%7}, {%8,%9}, {%0,%1,%2,%3};"
        : "+f"(d0), "+f"(d1), "+f"(d2), "+f"(d3)
        : "r"(a0), "r"(a1), "r"(a2), "r"(a3), "r"(b0), "r"(b1));
}

__global__ __launch_bounds__(256, 2)
void bmm_mma_kernel(const float* __restrict__ x1,
                    const float* __restrict__ x2,
                    const float* __restrict__ cptr,
                    float* __restrict__ out) {
    // Union buffer: staging A(4352 w) + B(4352 w) = 8704 words;
    // epilogue C chunk needs 64*132 = 8448 words. Reused after mainloop.
    __shared__ uint32_t sbuf[2 * TILE_WORDS];
    uint32_t* As = sbuf;
    uint32_t* Bs = sbuf + TILE_WORDS;

    const int tid = threadIdx.x;
    const int wid = tid >> 5;
    const int lid = tid & 31;
    const int g   = lid >> 2;     // groupID 0..7
    const int t4  = lid & 3;      // thread-in-group 0..3
    const int warp_m = wid & 3;   // 0..3  (32-row block)
    const int warp_n = wid >> 2;  // 0..1  (64-col block)
    const int b = blockIdx.z;
    const int N = 4096, M = 4096;

    // ---- Stage tiles: gmem fp32 -> tf32 -> permuted smem ----
    // newcol(c) = (c&3)*8 + (c>>2): float4 at cols 4q..4q+3 scatters to
    // words q, q+8, q+16, q+24 of the row.
    const float* a_base = x1 + ((size_t)b * N + (size_t)blockIdx.y * TILE) * DDIM;
    const float* b_base = x2 + ((size_t)b * M + (size_t)blockIdx.x * TILE) * DDIM;
    #pragma unroll
    for (int i = 0; i < 4; i++) {
        int s = tid + i * 256;        // 0..1023
        int row = s >> 3;             // 0..127
        int q   = s & 7;              // float4 index within row
        float4 va = *(const float4*)(a_base + (size_t)row * DDIM + q * 4);
        uint32_t* da = &As[row * ROW_WORDS + q];
        da[0]  = f32_to_tf32(va.x);
        da[8]  = f32_to_tf32(va.y);
        da[16] = f32_to_tf32(va.z);
        da[24] = f32_to_tf32(va.w);
        float4 vb = *(const float4*)(b_base + (size_t)row * DDIM + q * 4);
        uint32_t* db = &Bs[row * ROW_WORDS + q];
        db[0]  = f32_to_tf32(vb.x);
        db[8]  = f32_to_tf32(vb.y);
        db[16] = f32_to_tf32(vb.z);
        db[24] = f32_to_tf32(vb.w);
    }
    const float cbias = cptr[0];
    __syncthreads();

    // ---- MMA mainloop ----
    float acc[2][8][4];
    #pragma unroll
    for (int mt = 0; mt < 2; mt++)
        #pragma unroll
        for (int nt = 0; nt < 8; nt++)
            #pragma unroll
            for (int r = 0; r < 4; r++)
                acc[mt][nt][r] = 0.0f;

    const int frag_word = t4 * 8;   // + 2j selects the k-step pair
    #pragma unroll
    for (int j = 0; j < 4; j++) {
        uint2 apair[2][2];
        #pragma unroll
        for (int mt = 0; mt < 2; mt++) {
            int row0 = warp_m * 32 + mt * 16 + g;
            apair[mt][0] = *(const uint2*)&As[row0 * ROW_WORDS + frag_word + 2 * j];
            apair[mt][1] = *(const uint2*)&As[(row0 + 8) * ROW_WORDS + frag_word + 2 * j];
        }
        uint2 bpair[8];
        #pragma unroll
        for (int nt = 0; nt < 8; nt++) {
            int brow = warp_n * 64 + nt * 8 + g;
            bpair[nt] = *(const uint2*)&Bs[brow * ROW_WORDS + frag_word + 2 * j];
        }
        #pragma unroll
        for (int mt = 0; mt < 2; mt++)
            #pragma unroll
            for (int nt = 0; nt < 8; nt++)
                mma_tf32_16x8x8(acc[mt][nt][0], acc[mt][nt][1],
                                acc[mt][nt][2], acc[mt][nt][3],
                                apair[mt][0].x, apair[mt][1].x,
                                apair[mt][0].y, apair[mt][1].y,
                                bpair[nt].x, bpair[nt].y);
    }

    // ---- Epilogue: acc -> smem (bias added) -> coalesced STG.128 ----
    // 2 chunks of 64 rows. Chunk p is produced by warps with warp_m>>1 == p,
    // then all 8 warps store it with full 512B-per-instruction rows.
    float* cs = (float*)sbuf;
    const int my_chunk = warp_m >> 1;
    const size_t gcol = (size_t)blockIdx.x * TILE + lid * 4;
    #pragma unroll
    for (int chunk = 0; chunk < 2; chunk++) {
        __syncthreads();   // sbuf free: mainloop LDS (iter 0) / prior LDS (iter 1)
        if (my_chunk == chunk) {
            const int rbase = (warp_m & 1) * 32;
            #pragma unroll
            for (int mt = 0; mt < 2; mt++) {
                int r0 = rbase + mt * 16 + g;
                #pragma unroll
                for (int nt = 0; nt < 8; nt++) {
                    int c0 = warp_n * 64 + nt * 8 + 2 * t4;
                    *(float2*)&cs[r0 * C_STRIDE + c0] =
                        make_float2(acc[mt][nt][0] + cbias, acc[mt][nt][1] + cbias);
                    *(float2*)&cs[(r0 + 8) * C_STRIDE + c0] =
                        make_float2(acc[mt][nt][2] + cbias, acc[mt][nt][3] + cbias);
                }
            }
        }
        __syncthreads();
        const size_t grow0 = (size_t)b * N + (size_t)blockIdx.y * TILE + chunk * 64;
        #pragma unroll
        for (int i = 0; i < 8; i++) {
            int r = i * 8 + wid;
            float4 v = *(const float4*)&cs[r * C_STRIDE + lid * 4];
            *(float4*)(out + (grow0 + r) * M + gcol) = v;
        }
    }
}

extern "C" void kernel_launch(void* const* d_in, const int* in_sizes, int n_in,
                              void* d_out, int out_size) {
    const float* x1  = (const float*)d_in[0];   // [4, 4096, 32]
    const float* x2  = (const float*)d_in[1];   // [4, 4096, 32]
    const float* cst = (const float*)d_in[2];   // [1]
    float* out       = (float*)d_out;           // [4, 4096, 4096]

    dim3 grid(4096 / TILE, 4096 / TILE, 4);
    bmm_mma_kernel<<<grid, 256>>>(x1, x2, cst, out);
}